// round 1
// baseline (speedup 1.0000x reference)
#include <cuda_runtime.h>

#define N_Q 1024
#define N_O 2048
#define LATENT 128
#define HEADS 4

typedef unsigned long long ull;

// ---------------- scratch (static device globals; no allocation) ----------------
__device__ float g_v[N_O * LATENT];                      // 1 MB   value vectors
__device__ float g_bo[N_O * LATENT];                     // 1 MB   per-obs linear term
__device__ float g_aq[N_Q * LATENT];                     // 512 KB per-query linear term (incl b1)
__device__ float g_logits[(size_t)N_Q * N_O * HEADS];    // 32 MB  pairwise logits
__device__ float g_m[N_Q * HEADS];                       // softmax max
__device__ float g_is[N_Q * HEADS];                      // softmax 1/sum
__device__ float g_part[4 * N_Q * LATENT];               // 2 MB   aggregation partials

// ---------------- packed f32x2 helpers ----------------
__device__ __forceinline__ ull fma2(ull a, ull b, ull c) {
    ull d; asm("fma.rn.f32x2 %0, %1, %2, %3;" : "=l"(d) : "l"(a), "l"(b), "l"(c)); return d;
}
__device__ __forceinline__ ull add2(ull a, ull b) {
    ull d; asm("add.rn.f32x2 %0, %1, %2;" : "=l"(d) : "l"(a), "l"(b)); return d;
}
__device__ __forceinline__ ull relu2(ull a) {
    ull d;
    asm("{\n\t"
        ".reg .f32 lo, hi;\n\t"
        "mov.b64 {lo, hi}, %1;\n\t"
        "max.f32 lo, lo, 0f00000000;\n\t"
        "max.f32 hi, hi, 0f00000000;\n\t"
        "mov.b64 %0, {lo, hi};\n\t"
        "}" : "=l"(d) : "l"(a));
    return d;
}
__device__ __forceinline__ ull pack2(float x, float y) {
    ull d; asm("mov.b64 %0, {%1, %2};" : "=l"(d) : "f"(x), "f"(y)); return d;
}
__device__ __forceinline__ float2 unpack2(ull a) {
    float2 f; asm("mov.b64 {%0, %1}, %2;" : "=f"(f.x), "=f"(f.y) : "l"(a)); return f;
}

// ---------------- kernel 1: per-obs precompute (LayerNorm -> v, and bo) ----------------
// grid: N_O/16 blocks, 128 threads (thread = latent index)
__global__ void pre_o_kernel(const float* __restrict__ h_obs,
                             const float* __restrict__ pos_obs,
                             const float* __restrict__ W1,
                             const float* __restrict__ ln_gamma,
                             const float* __restrict__ ln_beta,
                             const float* __restrict__ Wv,
                             const float* __restrict__ bv) {
    __shared__ float s_hn[16][LATENT];
    __shared__ float s_red[2][4];
    int l = threadIdx.x;
    int w = l >> 5, lane = l & 31;

    float bw0 = W1[(3 + 0) * LATENT + l] - W1[(6 + 0) * LATENT + l];
    float bw1 = W1[(3 + 1) * LATENT + l] - W1[(6 + 1) * LATENT + l];
    float bw2 = W1[(3 + 2) * LATENT + l] - W1[(6 + 2) * LATENT + l];
    float gam = ln_gamma[l], bet = ln_beta[l];

    for (int oi = 0; oi < 16; oi++) {
        int o = blockIdx.x * 16 + oi;
        float h = h_obs[o * LATENT + l];
        float s1 = h, s2 = h * h;
        #pragma unroll
        for (int off = 16; off; off >>= 1) {
            s1 += __shfl_xor_sync(0xffffffffu, s1, off);
            s2 += __shfl_xor_sync(0xffffffffu, s2, off);
        }
        if (lane == 0) { s_red[0][w] = s1; s_red[1][w] = s2; }
        __syncthreads();
        float S1 = s_red[0][0] + s_red[0][1] + s_red[0][2] + s_red[0][3];
        float S2 = s_red[1][0] + s_red[1][1] + s_red[1][2] + s_red[1][3];
        __syncthreads();
        float mu = S1 * (1.0f / LATENT);
        float var = S2 * (1.0f / LATENT) - mu * mu;
        float hn = (h - mu) * rsqrtf(var + 1e-5f) * gam + bet;
        s_hn[oi][l] = hn;
        float p0 = pos_obs[o * 3 + 0], p1 = pos_obs[o * 3 + 1], p2 = pos_obs[o * 3 + 2];
        g_bo[o * LATENT + l] = p0 * bw0 + p1 * bw1 + p2 * bw2;
    }
    __syncthreads();

    float acc[16];
    float b = bv[l];
    #pragma unroll
    for (int oi = 0; oi < 16; oi++) acc[oi] = b;
    for (int k = 0; k < LATENT; k++) {
        float wv = Wv[k * LATENT + l];
        #pragma unroll
        for (int oi = 0; oi < 16; oi++) acc[oi] += s_hn[oi][k] * wv;
    }
    #pragma unroll
    for (int oi = 0; oi < 16; oi++)
        g_v[(blockIdx.x * 16 + oi) * LATENT + l] = acc[oi];
}

// ---------------- kernel 2: per-query precompute (aq, incl b1) ----------------
// grid: N_Q/32 blocks, 128 threads
__global__ void pre_q_kernel(const float* __restrict__ pos_query,
                             const float* __restrict__ W1,
                             const float* __restrict__ b1) {
    int l = threadIdx.x;
    float aw0 = W1[0 * LATENT + l] + W1[(6 + 0) * LATENT + l];
    float aw1 = W1[1 * LATENT + l] + W1[(6 + 1) * LATENT + l];
    float aw2 = W1[2 * LATENT + l] + W1[(6 + 2) * LATENT + l];
    float bb = b1[l];
    for (int qi = 0; qi < 32; qi++) {
        int q = blockIdx.x * 32 + qi;
        float p0 = pos_query[q * 3 + 0], p1 = pos_query[q * 3 + 1], p2 = pos_query[q * 3 + 2];
        g_aq[q * LATENT + l] = bb + p0 * aw0 + p1 * aw1 + p2 * aw2;
    }
}

// ---------------- kernel 3: pairwise logits (THE hot kernel) ----------------
// grid: (N_O/32, N_Q/32), 256 threads. warp = 4 queries, lanes = 32 obs.
__global__ __launch_bounds__(256) void logits_kernel(
    const float* __restrict__ pos_query, const float* __restrict__ pos_obs,
    const int* __restrict__ query_batch, const int* __restrict__ obs_batch,
    const float* __restrict__ W1, const float* __restrict__ W2,
    const float* __restrict__ b2) {
    __shared__ ulonglong2 s_bo[32][33];   // [lgroup][o]  bo[o][4lg..4lg+3], padded vs bank conflicts
    __shared__ ulonglong2 s_aq[32][32];   // [q][lgroup]
    __shared__ float s_d[32][32];         // [q][o] pair distances
    __shared__ ulonglong2 s_w2[32][4];    // [lgroup][h]: (W2[4lg,h],W2[4lg+1,h] | W2[4lg+2,h],W2[4lg+3,h])
    __shared__ ulonglong2 s_wd[32];       // wd[l] = W1[9][l]
    __shared__ float s_b2[4];
    __shared__ int s_qb[32], s_ob[32];
    __shared__ float s_pq[32][3], s_po[32][3];

    int t = threadIdx.x;
    int o0 = blockIdx.x * 32, q0 = blockIdx.y * 32;

    // stage aq tile (coalesced, conflict-free)
    const float4* aq4 = (const float4*)g_aq;
    for (int i = t; i < 1024; i += 256) {
        int q = i >> 5, lg = i & 31;
        ((float4*)s_aq)[q * 32 + lg] = aq4[(q0 + q) * 32 + lg];
    }
    // stage bo tile transposed (coalesced LDG; padded SMEM kills STS conflicts)
    const float4* bo4 = (const float4*)g_bo;
    for (int i = t; i < 1024; i += 256) {
        int o = i >> 5, lg = i & 31;
        *((float4*)&s_bo[lg][o]) = bo4[(o0 + o) * 32 + lg];
    }
    // W2 repack
    for (int i = t; i < 512; i += 256) {
        int l = i >> 2, h = i & 3;
        ((float*)s_w2)[(l >> 2) * 16 + h * 4 + (l & 3)] = W2[l * 4 + h];
    }
    if (t < 128) ((float*)s_wd)[t] = W1[9 * LATENT + t];
    if (t < 4) s_b2[t] = b2[t];
    if (t < 32) { s_qb[t] = query_batch[q0 + t]; s_ob[t] = obs_batch[o0 + t]; }
    for (int i = t; i < 96; i += 256) {
        int r = i / 3, p = i % 3;
        s_pq[r][p] = pos_query[(q0 + r) * 3 + p];
        s_po[r][p] = pos_obs[(o0 + r) * 3 + p];
    }
    __syncthreads();
    // pair distances
    for (int i = t; i < 1024; i += 256) {
        int q = i >> 5, o = i & 31;
        float dx = s_pq[q][0] - s_po[o][0];
        float dy = s_pq[q][1] - s_po[o][1];
        float dz = s_pq[q][2] - s_po[o][2];
        s_d[q][o] = sqrtf(dx * dx + dy * dy + dz * dz);
    }
    __syncthreads();

    int warp = t >> 5, lane = t & 31;
    int qb4 = warp << 2;

    ull d2[4];
    #pragma unroll
    for (int q = 0; q < 4; q++) {
        float dv = s_d[qb4 + q][lane];
        d2[q] = pack2(dv, dv);
    }
    ull acc[4][4];
    #pragma unroll
    for (int q = 0; q < 4; q++)
        #pragma unroll
        for (int h = 0; h < 4; h++) acc[q][h] = 0ull;

    #pragma unroll 4
    for (int lg = 0; lg < 32; lg++) {
        ulonglong2 bo = s_bo[lg][lane];
        ulonglong2 wd = s_wd[lg];
        ulonglong2 w0 = s_w2[lg][0], w1 = s_w2[lg][1], w2v = s_w2[lg][2], w3 = s_w2[lg][3];
        #pragma unroll
        for (int q = 0; q < 4; q++) {
            ulonglong2 aq = s_aq[qb4 + q][lg];
            ull ta = relu2(fma2(wd.x, d2[q], add2(aq.x, bo.x)));
            ull tb = relu2(fma2(wd.y, d2[q], add2(aq.y, bo.y)));
            acc[q][0] = fma2(ta, w0.x, acc[q][0]);
            acc[q][1] = fma2(ta, w1.x, acc[q][1]);
            acc[q][2] = fma2(ta, w2v.x, acc[q][2]);
            acc[q][3] = fma2(ta, w3.x, acc[q][3]);
            acc[q][0] = fma2(tb, w0.y, acc[q][0]);
            acc[q][1] = fma2(tb, w1.y, acc[q][1]);
            acc[q][2] = fma2(tb, w2v.y, acc[q][2]);
            acc[q][3] = fma2(tb, w3.y, acc[q][3]);
        }
    }

    float4* Lout = (float4*)g_logits;
    #pragma unroll
    for (int q = 0; q < 4; q++) {
        bool ok = (s_qb[qb4 + q] == s_ob[lane]);
        float4 r;
        if (ok) {
            float2 a0 = unpack2(acc[q][0]);
            float2 a1 = unpack2(acc[q][1]);
            float2 a2 = unpack2(acc[q][2]);
            float2 a3 = unpack2(acc[q][3]);
            r.x = a0.x + a0.y + s_b2[0];
            r.y = a1.x + a1.y + s_b2[1];
            r.z = a2.x + a2.y + s_b2[2];
            r.w = a3.x + a3.y + s_b2[3];
        } else {
            r.x = r.y = r.z = r.w = -1e30f;
        }
        Lout[(size_t)(q0 + qb4 + q) * N_O + o0 + lane] = r;
    }
}

// ---------------- kernel 4: softmax stats per (q, head) ----------------
// grid: N_Q blocks, 256 threads
__global__ void stats_kernel() {
    int q = blockIdx.x, t = threadIdx.x;
    int w = t >> 5, lane = t & 31;
    const float4* L = ((const float4*)g_logits) + (size_t)q * N_O;
    __shared__ float sr[8][4];

    float m0 = -3e38f, m1 = -3e38f, m2 = -3e38f, m3 = -3e38f;
    for (int o = t; o < N_O; o += 256) {
        float4 v = L[o];
        m0 = fmaxf(m0, v.x); m1 = fmaxf(m1, v.y);
        m2 = fmaxf(m2, v.z); m3 = fmaxf(m3, v.w);
    }
    #pragma unroll
    for (int off = 16; off; off >>= 1) {
        m0 = fmaxf(m0, __shfl_xor_sync(0xffffffffu, m0, off));
        m1 = fmaxf(m1, __shfl_xor_sync(0xffffffffu, m1, off));
        m2 = fmaxf(m2, __shfl_xor_sync(0xffffffffu, m2, off));
        m3 = fmaxf(m3, __shfl_xor_sync(0xffffffffu, m3, off));
    }
    if (lane == 0) { sr[w][0] = m0; sr[w][1] = m1; sr[w][2] = m2; sr[w][3] = m3; }
    __syncthreads();
    m0 = sr[0][0]; m1 = sr[0][1]; m2 = sr[0][2]; m3 = sr[0][3];
    #pragma unroll
    for (int i = 1; i < 8; i++) {
        m0 = fmaxf(m0, sr[i][0]); m1 = fmaxf(m1, sr[i][1]);
        m2 = fmaxf(m2, sr[i][2]); m3 = fmaxf(m3, sr[i][3]);
    }
    __syncthreads();

    float s0 = 0, s1 = 0, s2 = 0, s3 = 0;
    for (int o = t; o < N_O; o += 256) {
        float4 v = L[o];
        s0 += __expf(v.x - m0); s1 += __expf(v.y - m1);
        s2 += __expf(v.z - m2); s3 += __expf(v.w - m3);
    }
    #pragma unroll
    for (int off = 16; off; off >>= 1) {
        s0 += __shfl_xor_sync(0xffffffffu, s0, off);
        s1 += __shfl_xor_sync(0xffffffffu, s1, off);
        s2 += __shfl_xor_sync(0xffffffffu, s2, off);
        s3 += __shfl_xor_sync(0xffffffffu, s3, off);
    }
    if (lane == 0) { sr[w][0] = s0; sr[w][1] = s1; sr[w][2] = s2; sr[w][3] = s3; }
    __syncthreads();
    if (t == 0) {
        float S0 = 0, S1 = 0, S2 = 0, S3 = 0;
        #pragma unroll
        for (int i = 0; i < 8; i++) { S0 += sr[i][0]; S1 += sr[i][1]; S2 += sr[i][2]; S3 += sr[i][3]; }
        g_m[q * 4 + 0] = m0; g_m[q * 4 + 1] = m1; g_m[q * 4 + 2] = m2; g_m[q * 4 + 3] = m3;
        g_is[q * 4 + 0] = 1.0f / S0; g_is[q * 4 + 1] = 1.0f / S1;
        g_is[q * 4 + 2] = 1.0f / S2; g_is[q * 4 + 3] = 1.0f / S3;
    }
}

// ---------------- kernel 5: weighted aggregation (partials over o-segments) ----------------
// grid: (N_Q/8, 4 segments), 128 threads (thread = latent)
__global__ __launch_bounds__(128) void agg_kernel() {
    __shared__ float s_w[8][4][32];   // [q][h][o]
    __shared__ float s_m[8][4], s_is[8][4];
    int l = threadIdx.x, h = l >> 5;
    int q0 = blockIdx.x * 8;
    int seg = blockIdx.y;
    int obase = seg * (N_O / 4);

    if (l < 32) {
        int q = l >> 2, hh = l & 3;
        s_m[q][hh] = g_m[(q0 + q) * 4 + hh];
        s_is[q][hh] = g_is[(q0 + q) * 4 + hh];
    }
    __syncthreads();

    float acc[8];
    #pragma unroll
    for (int q = 0; q < 8; q++) acc[q] = 0.0f;

    for (int ot = 0; ot < (N_O / 4) / 32; ot++) {
        int oo = obase + ot * 32;
        __syncthreads();
        for (int i = l; i < 256; i += 128) {
            int q = i >> 5, o = i & 31;
            float4 v = ((const float4*)g_logits)[(size_t)(q0 + q) * N_O + oo + o];
            s_w[q][0][o] = __expf(v.x - s_m[q][0]) * s_is[q][0];
            s_w[q][1][o] = __expf(v.y - s_m[q][1]) * s_is[q][1];
            s_w[q][2][o] = __expf(v.z - s_m[q][2]) * s_is[q][2];
            s_w[q][3][o] = __expf(v.w - s_m[q][3]) * s_is[q][3];
        }
        __syncthreads();
        float vv[32];
        #pragma unroll
        for (int o = 0; o < 32; o++) vv[o] = g_v[(oo + o) * LATENT + l];
        #pragma unroll
        for (int q = 0; q < 8; q++) {
            const float4* wq = (const float4*)s_w[q][h];
            #pragma unroll
            for (int og = 0; og < 8; og++) {
                float4 wv = wq[og];
                acc[q] += wv.x * vv[og * 4 + 0] + wv.y * vv[og * 4 + 1]
                        + wv.z * vv[og * 4 + 2] + wv.w * vv[og * 4 + 3];
            }
        }
    }
    #pragma unroll
    for (int q = 0; q < 8; q++)
        g_part[(size_t)seg * N_Q * LATENT + (q0 + q) * LATENT + l] = acc[q];
}

// ---------------- kernel 6: finalize (sum 4 partials) ----------------
__global__ void finalize_kernel(float* __restrict__ out) {
    int i = blockIdx.x * 256 + threadIdx.x;
    const int NL = N_Q * LATENT;
    out[i] = g_part[i] + g_part[NL + i] + g_part[2 * NL + i] + g_part[3 * NL + i];
}

// ---------------- launch ----------------
extern "C" void kernel_launch(void* const* d_in, const int* in_sizes, int n_in,
                              void* d_out, int out_size) {
    const float* h_obs      = (const float*)d_in[0];
    const float* pos_obs    = (const float*)d_in[1];
    const float* pos_query  = (const float*)d_in[2];
    const int*   obs_batch  = (const int*)d_in[3];
    const int*   query_batch= (const int*)d_in[4];
    const float* W1         = (const float*)d_in[5];
    const float* b1         = (const float*)d_in[6];
    const float* W2         = (const float*)d_in[7];
    const float* b2         = (const float*)d_in[8];
    const float* ln_gamma   = (const float*)d_in[9];
    const float* ln_beta    = (const float*)d_in[10];
    const float* Wv         = (const float*)d_in[11];
    const float* bv         = (const float*)d_in[12];
    float* out = (float*)d_out;

    pre_o_kernel<<<N_O / 16, 128>>>(h_obs, pos_obs, W1, ln_gamma, ln_beta, Wv, bv);
    pre_q_kernel<<<N_Q / 32, 128>>>(pos_query, W1, b1);
    dim3 gl(N_O / 32, N_Q / 32);
    logits_kernel<<<gl, 256>>>(pos_query, pos_obs, query_batch, obs_batch, W1, W2, b2);
    stats_kernel<<<N_Q, 256>>>();
    agg_kernel<<<dim3(N_Q / 8, 4), 128>>>();
    finalize_kernel<<<(N_Q * LATENT) / 256, 256>>>(out);
}

// round 2
// speedup vs baseline: 1.0120x; 1.0120x over previous
#include <cuda_runtime.h>

#define N_Q 1024
#define N_O 2048
#define LATENT 128
#define HEADS 4
#define SEGS 8
#define SEG_O (N_O / SEGS)          // 256
#define O_TILE 32
#define N_TILES (SEG_O / O_TILE)    // 8

typedef unsigned long long ull;

// ---------------- scratch (static device globals; no allocation) ----------------
__device__ float g_v[N_O * LATENT];                    // value vectors
__device__ float g_bo[N_O * LATENT];                   // per-obs linear term
__device__ float g_aq[N_Q * LATENT];                   // per-query linear term (incl b1)
__device__ float g_m2[SEGS * N_Q * HEADS];             // per-segment running max
__device__ float g_s2[SEGS * N_Q * HEADS];             // per-segment exp-sum
__device__ float g_acc[SEGS * N_Q * LATENT];           // per-segment weighted partials (4MB)

// ---------------- packed f32x2 helpers ----------------
__device__ __forceinline__ ull fma2(ull a, ull b, ull c) {
    ull d; asm("fma.rn.f32x2 %0, %1, %2, %3;" : "=l"(d) : "l"(a), "l"(b), "l"(c)); return d;
}
__device__ __forceinline__ ull add2(ull a, ull b) {
    ull d; asm("add.rn.f32x2 %0, %1, %2;" : "=l"(d) : "l"(a), "l"(b)); return d;
}
__device__ __forceinline__ ull relu2(ull a) {
    ull d;
    asm("{\n\t"
        ".reg .f32 lo, hi;\n\t"
        "mov.b64 {lo, hi}, %1;\n\t"
        "max.f32 lo, lo, 0f00000000;\n\t"
        "max.f32 hi, hi, 0f00000000;\n\t"
        "mov.b64 %0, {lo, hi};\n\t"
        "}" : "=l"(d) : "l"(a));
    return d;
}
__device__ __forceinline__ ull pack2(float x, float y) {
    ull d; asm("mov.b64 %0, {%1, %2};" : "=l"(d) : "f"(x), "f"(y)); return d;
}
__device__ __forceinline__ float2 unpack2(ull a) {
    float2 f; asm("mov.b64 {%0, %1}, %2;" : "=f"(f.x), "=f"(f.y) : "l"(a)); return f;
}

// ---------------- kernel 1: per-obs precompute (LayerNorm -> v, and bo) ----------------
__global__ void pre_o_kernel(const float* __restrict__ h_obs,
                             const float* __restrict__ pos_obs,
                             const float* __restrict__ W1,
                             const float* __restrict__ ln_gamma,
                             const float* __restrict__ ln_beta,
                             const float* __restrict__ Wv,
                             const float* __restrict__ bv) {
    __shared__ float s_hn[16][LATENT];
    __shared__ float s_red[2][4];
    int l = threadIdx.x;
    int w = l >> 5, lane = l & 31;

    float bw0 = W1[(3 + 0) * LATENT + l] - W1[(6 + 0) * LATENT + l];
    float bw1 = W1[(3 + 1) * LATENT + l] - W1[(6 + 1) * LATENT + l];
    float bw2 = W1[(3 + 2) * LATENT + l] - W1[(6 + 2) * LATENT + l];
    float gam = ln_gamma[l], bet = ln_beta[l];

    for (int oi = 0; oi < 16; oi++) {
        int o = blockIdx.x * 16 + oi;
        float h = h_obs[o * LATENT + l];
        float s1 = h, s2 = h * h;
        #pragma unroll
        for (int off = 16; off; off >>= 1) {
            s1 += __shfl_xor_sync(0xffffffffu, s1, off);
            s2 += __shfl_xor_sync(0xffffffffu, s2, off);
        }
        if (lane == 0) { s_red[0][w] = s1; s_red[1][w] = s2; }
        __syncthreads();
        float S1 = s_red[0][0] + s_red[0][1] + s_red[0][2] + s_red[0][3];
        float S2 = s_red[1][0] + s_red[1][1] + s_red[1][2] + s_red[1][3];
        __syncthreads();
        float mu = S1 * (1.0f / LATENT);
        float var = S2 * (1.0f / LATENT) - mu * mu;
        float hn = (h - mu) * rsqrtf(var + 1e-5f) * gam + bet;
        s_hn[oi][l] = hn;
        float p0 = pos_obs[o * 3 + 0], p1 = pos_obs[o * 3 + 1], p2 = pos_obs[o * 3 + 2];
        g_bo[o * LATENT + l] = p0 * bw0 + p1 * bw1 + p2 * bw2;
    }
    __syncthreads();

    float acc[16];
    float b = bv[l];
    #pragma unroll
    for (int oi = 0; oi < 16; oi++) acc[oi] = b;
    for (int k = 0; k < LATENT; k++) {
        float wv = Wv[k * LATENT + l];
        #pragma unroll
        for (int oi = 0; oi < 16; oi++) acc[oi] += s_hn[oi][k] * wv;
    }
    #pragma unroll
    for (int oi = 0; oi < 16; oi++)
        g_v[(blockIdx.x * 16 + oi) * LATENT + l] = acc[oi];
}

// ---------------- kernel 2: per-query precompute (aq, incl b1) ----------------
__global__ void pre_q_kernel(const float* __restrict__ pos_query,
                             const float* __restrict__ W1,
                             const float* __restrict__ b1) {
    int l = threadIdx.x;
    float aw0 = W1[0 * LATENT + l] + W1[(6 + 0) * LATENT + l];
    float aw1 = W1[1 * LATENT + l] + W1[(6 + 1) * LATENT + l];
    float aw2 = W1[2 * LATENT + l] + W1[(6 + 2) * LATENT + l];
    float bb = b1[l];
    for (int qi = 0; qi < 32; qi++) {
        int q = blockIdx.x * 32 + qi;
        float p0 = pos_query[q * 3 + 0], p1 = pos_query[q * 3 + 1], p2 = pos_query[q * 3 + 2];
        g_aq[q * LATENT + l] = bb + p0 * aw0 + p1 * aw1 + p2 * aw2;
    }
}

// ---------------- kernel 3: fused logits + online softmax + aggregation ----------------
// grid: (N_Q/32, SEGS), 256 threads.
// Phase1 layout: warp = 4 queries x 32 obs lanes. Phase2: thread = (q-half, latent).
__global__ __launch_bounds__(256, 2) void fused_kernel(
    const float* __restrict__ pos_query, const float* __restrict__ pos_obs,
    const int* __restrict__ query_batch, const int* __restrict__ obs_batch,
    const float* __restrict__ W1, const float* __restrict__ W2) {

    // s_pool aliases: bo tile (phase1 input) and w tile (phase1 output / phase2 input)
    __shared__ char s_pool[32 * 33 * 16];                     // 16896 B
    __shared__ ulonglong2 s_aq[32][32];                       // [q][lg]
    __shared__ float s_f[32][4];                              // rescale factors
    __shared__ ulonglong2 s_w2[32][4];                        // [lg][h]
    __shared__ ulonglong2 s_wd[32];
    __shared__ float s_pq[32][3];
    __shared__ int s_qb[32];
    __shared__ float s_po[SEG_O][3];
    __shared__ int s_ob[SEG_O];

    ulonglong2 (*s_bo)[33] = (ulonglong2(*)[33])s_pool;       // [lg][o]
    float (*s_w)[4][O_TILE] = (float(*)[4][O_TILE])s_pool;    // [q][h][o]

    int t = threadIdx.x;
    int q0 = blockIdx.x * 32;
    int seg = blockIdx.y;
    int ob0 = seg * SEG_O;

    // ---- one-time staging ----
    const float4* aq4 = (const float4*)g_aq;
    for (int i = t; i < 1024; i += 256) {
        int q = i >> 5, lg = i & 31;
        ((float4*)s_aq)[q * 32 + lg] = aq4[(q0 + q) * 32 + lg];
    }
    for (int i = t; i < 512; i += 256) {
        int l = i >> 2, h = i & 3;
        ((float*)s_w2)[(l >> 2) * 16 + h * 4 + (l & 3)] = W2[l * 4 + h];
    }
    if (t < 128) ((float*)s_wd)[t] = W1[9 * LATENT + t];
    if (t < 32) s_qb[t] = query_batch[q0 + t];
    for (int i = t; i < 96; i += 256) {
        int r = i / 3, p = i % 3;
        s_pq[r][p] = pos_query[(q0 + r) * 3 + p];
    }
    for (int i = t; i < SEG_O * 3; i += 256) {
        int r = i / 3, p = i % 3;
        s_po[r][p] = pos_obs[(ob0 + r) * 3 + p];
    }
    for (int i = t; i < SEG_O; i += 256) s_ob[i] = obs_batch[ob0 + i];

    int warp = t >> 5, lane = t & 31;
    int qb4 = warp << 2;
    // phase-2 mapping
    int l2 = t & 127, h2 = l2 >> 5;
    int qbase = (t >> 7) * 16;

    float m_run[4][4], s_run[4][4];
    #pragma unroll
    for (int q = 0; q < 4; q++)
        #pragma unroll
        for (int h = 0; h < 4; h++) { m_run[q][h] = -3e38f; s_run[q][h] = 0.0f; }
    ull acc2[16];
    #pragma unroll
    for (int i = 0; i < 16; i++) acc2[i] = 0ull;

    const float4* bo4 = (const float4*)g_bo;

    for (int tile = 0; tile < N_TILES; tile++) {
        int oo = tile * O_TILE;          // local obs offset within segment
        int og0 = ob0 + oo;              // global obs offset

        __syncthreads();   // previous phase2 done reading s_w before we overwrite pool
        // stage bo tile transposed
        for (int i = t; i < 1024; i += 256) {
            int o = i >> 5, lg = i & 31;
            *((float4*)&s_bo[lg][o]) = bo4[(og0 + o) * 32 + lg];
        }
        __syncthreads();

        // ---- phase 1: logits + online softmax ----
        ull d2[4];
        bool ok[4];
        {
            float px = s_po[oo + lane][0], py = s_po[oo + lane][1], pz = s_po[oo + lane][2];
            int obv = s_ob[oo + lane];
            #pragma unroll
            for (int q = 0; q < 4; q++) {
                float dx = s_pq[qb4 + q][0] - px;
                float dy = s_pq[qb4 + q][1] - py;
                float dz = s_pq[qb4 + q][2] - pz;
                float dv = __fsqrt_rn(dx * dx + dy * dy + dz * dz);
                d2[q] = pack2(dv, dv);
                ok[q] = (s_qb[qb4 + q] == obv);
            }
        }
        ull acc1[4][4];
        #pragma unroll
        for (int q = 0; q < 4; q++)
            #pragma unroll
            for (int h = 0; h < 4; h++) acc1[q][h] = 0ull;

        #pragma unroll 4
        for (int lg = 0; lg < 32; lg++) {
            ulonglong2 bo = s_bo[lg][lane];
            ulonglong2 wd = s_wd[lg];
            ulonglong2 w0 = s_w2[lg][0], w1 = s_w2[lg][1], w2v = s_w2[lg][2], w3 = s_w2[lg][3];
            #pragma unroll
            for (int q = 0; q < 4; q++) {
                ulonglong2 aq = s_aq[qb4 + q][lg];
                ull ta = relu2(fma2(wd.x, d2[q], add2(aq.x, bo.x)));
                ull tb = relu2(fma2(wd.y, d2[q], add2(aq.y, bo.y)));
                acc1[q][0] = fma2(ta, w0.x, acc1[q][0]);
                acc1[q][1] = fma2(ta, w1.x, acc1[q][1]);
                acc1[q][2] = fma2(ta, w2v.x, acc1[q][2]);
                acc1[q][3] = fma2(ta, w3.x, acc1[q][3]);
                acc1[q][0] = fma2(tb, w0.y, acc1[q][0]);
                acc1[q][1] = fma2(tb, w1.y, acc1[q][1]);
                acc1[q][2] = fma2(tb, w2v.y, acc1[q][2]);
                acc1[q][3] = fma2(tb, w3.y, acc1[q][3]);
            }
        }

        __syncthreads();   // all s_bo reads complete before s_w overwrites the pool

        float fsave[4][4];
        #pragma unroll
        for (int q = 0; q < 4; q++) {
            #pragma unroll
            for (int h = 0; h < 4; h++) {
                float2 a = unpack2(acc1[q][h]);
                float r = ok[q] ? (a.x + a.y) : -1e30f;   // b2 cancels in softmax
                float tm = r;
                #pragma unroll
                for (int off = 16; off; off >>= 1)
                    tm = fmaxf(tm, __shfl_xor_sync(0xffffffffu, tm, off));
                float mo = m_run[q][h];
                float mn = fmaxf(mo, tm);
                float f = __expf(mo - mn);
                float wv = __expf(r - mn);
                float sv = wv;
                #pragma unroll
                for (int off = 16; off; off >>= 1)
                    sv += __shfl_xor_sync(0xffffffffu, sv, off);
                s_run[q][h] = s_run[q][h] * f + sv;
                m_run[q][h] = mn;
                fsave[q][h] = f;
                s_w[qb4 + q][h][lane] = wv;
            }
        }
        // rescale factors to smem (one lane per (q,h))
        #pragma unroll
        for (int q = 0; q < 4; q++)
            #pragma unroll
            for (int h = 0; h < 4; h++)
                if (lane == q * 4 + h) s_f[qb4 + q][h] = fsave[q][h];

        __syncthreads();

        // ---- phase 2: rescale + weighted accumulation ----
        #pragma unroll
        for (int qi = 0; qi < 16; qi++) {
            float fq = s_f[qbase + qi][h2];
            acc2[qi] = fma2(acc2[qi], pack2(fq, fq), 0ull);
        }
        float vv[O_TILE];
        #pragma unroll
        for (int o = 0; o < O_TILE; o++)
            vv[o] = g_v[(og0 + o) * LATENT + l2];

        const ulonglong2* wv2 = (const ulonglong2*)s_pool;    // [q][h][o/4] as 2x f32x2
        #pragma unroll
        for (int o4 = 0; o4 < O_TILE / 4; o4++) {
            ull v01 = pack2(vv[o4 * 4 + 0], vv[o4 * 4 + 1]);
            ull v23 = pack2(vv[o4 * 4 + 2], vv[o4 * 4 + 3]);
            #pragma unroll
            for (int qi = 0; qi < 16; qi++) {
                ulonglong2 w4 = wv2[((qbase + qi) * 4 + h2) * (O_TILE / 4) + o4];
                acc2[qi] = fma2(w4.x, v01, acc2[qi]);
                acc2[qi] = fma2(w4.y, v23, acc2[qi]);
            }
        }
    }

    // ---- write per-segment partials ----
    #pragma unroll
    for (int q = 0; q < 4; q++)
        #pragma unroll
        for (int h = 0; h < 4; h++)
            if (lane == q * 4 + h) {
                int qg = q0 + qb4 + q;
                g_m2[(seg * N_Q + qg) * HEADS + h] = m_run[q][h];
                g_s2[(seg * N_Q + qg) * HEADS + h] = s_run[q][h];
            }
    #pragma unroll
    for (int qi = 0; qi < 16; qi++) {
        float2 a = unpack2(acc2[qi]);
        int qg = q0 + qbase + qi;
        g_acc[(seg * N_Q + qg) * LATENT + l2] = a.x + a.y;
    }
}

// ---------------- kernel 4: combine segment partials ----------------
__global__ void combine_kernel(float* __restrict__ out) {
    int idx = blockIdx.x * 256 + threadIdx.x;      // N_Q*LATENT threads
    int q = idx >> 7, l = idx & 127, h = l >> 5;
    float ms[SEGS];
    float M = -3e38f;
    #pragma unroll
    for (int sgi = 0; sgi < SEGS; sgi++) {
        ms[sgi] = g_m2[(sgi * N_Q + q) * HEADS + h];
        M = fmaxf(M, ms[sgi]);
    }
    float S = 0.0f, A = 0.0f;
    #pragma unroll
    for (int sgi = 0; sgi < SEGS; sgi++) {
        float e = __expf(ms[sgi] - M);
        S += g_s2[(sgi * N_Q + q) * HEADS + h] * e;
        A += g_acc[(sgi * N_Q + q) * LATENT + l] * e;
    }
    out[idx] = A / S;
}

// ---------------- launch ----------------
extern "C" void kernel_launch(void* const* d_in, const int* in_sizes, int n_in,
                              void* d_out, int out_size) {
    const float* h_obs      = (const float*)d_in[0];
    const float* pos_obs    = (const float*)d_in[1];
    const float* pos_query  = (const float*)d_in[2];
    const int*   obs_batch  = (const int*)d_in[3];
    const int*   query_batch= (const int*)d_in[4];
    const float* W1         = (const float*)d_in[5];
    const float* b1         = (const float*)d_in[6];
    const float* W2         = (const float*)d_in[7];
    const float* ln_gamma   = (const float*)d_in[9];
    const float* ln_beta    = (const float*)d_in[10];
    const float* Wv         = (const float*)d_in[11];
    const float* bv         = (const float*)d_in[12];
    float* out = (float*)d_out;

    pre_o_kernel<<<N_O / 16, 128>>>(h_obs, pos_obs, W1, ln_gamma, ln_beta, Wv, bv);
    pre_q_kernel<<<N_Q / 32, 128>>>(pos_query, W1, b1);
    fused_kernel<<<dim3(N_Q / 32, SEGS), 256>>>(pos_query, pos_obs, query_batch, obs_batch, W1, W2);
    combine_kernel<<<(N_Q * LATENT) / 256, 256>>>(out);
}